// round 6
// baseline (speedup 1.0000x reference)
#include <cuda_runtime.h>

#define BB 32
#define TT 512
#define DD 384
#define D4 96
#define OT 32              // output frames per tile
#define TUP 384            // upsample threads: 4 reps x 96 lanes
#define NOUT 8             // outputs per thread
#define WMAX 96
#define MAXTILES 128
#define NCHUNK 8
#define MARGIN 30.0f

// Scratch (__device__ globals: no allocations allowed)
__device__ float g_c[BB * TT];                 // gaussian centers (monotone per batch)
__device__ float g_rinv[BB * TT];              // 1/(rng+1e-6)
__device__ float4 g_colpart[NCHUNK][BB * D4];  // partial feats column sums
__device__ int2 g_win[BB * MAXTILES];          // per-tile token windows

#define FMA2(acc, a, b) \
    asm("fma.rn.f32x2 %0, %1, %2, %0;" : "+l"(acc) : "l"(a), "l"(b))

// ---------------------------------------------------------------------------
// Prep, grid (BB, NCHUNK): every block sums its 64-row feats chunk (partials);
// the ky==0 block additionally does the duration scan -> centers/rinv and the
// per-tile window binary searches.
// ---------------------------------------------------------------------------
__global__ __launch_bounds__(TT) void prep_kernel(const float* __restrict__ feats,
                                                  const float* __restrict__ rng,
                                                  const int* __restrict__ dur,
                                                  int ntiles) {
    int b = blockIdx.x, ky = blockIdx.y, t = threadIdx.x;
    int lane = t & 31, w = t >> 5;
    __shared__ float4 part[4][D4];
    __shared__ float sc[TT];
    __shared__ float wtot[16];

    // --- partial column sums: chunk ky = rows [ky*64, ky*64+64), 4 sub-slices ---
    if (t < 384) {
        int v = t % D4, sub = t / D4;
        const float4* f4 = (const float4*)feats + ((size_t)b * TT + ky * 64 + sub * 16) * D4 + v;
        float4 acc = make_float4(0.f, 0.f, 0.f, 0.f);
#pragma unroll
        for (int r = 0; r < 16; r++) {
            float4 f = f4[(size_t)r * D4];
            acc.x += f.x; acc.y += f.y; acc.z += f.z; acc.w += f.w;
        }
        part[sub][v] = acc;
    }
    __syncthreads();
    if (t < D4) {
        float4 acc = part[0][t];
#pragma unroll
        for (int s = 1; s < 4; s++) {
            float4 p = part[s][t];
            acc.x += p.x; acc.y += p.y; acc.z += p.z; acc.w += p.w;
        }
        g_colpart[ky][b * D4 + t] = acc;
    }

    if (ky != 0) return;

    // --- inclusive scan of durations -> centers ---
    float d = (float)dur[b * TT + t];
    float x = d;
#pragma unroll
    for (int off = 1; off < 32; off <<= 1) {
        float y = __shfl_up_sync(0xffffffffu, x, off);
        if (lane >= off) x += y;
    }
    if (lane == 31) wtot[w] = x;
    __syncthreads();
    if (w == 0 && t < 16) {
        float v = wtot[t];
#pragma unroll
        for (int off = 1; off < 16; off <<= 1) {
            float y = __shfl_up_sync(0x0000ffffu, v, off);
            if (t >= off) v += y;
        }
        wtot[t] = v;
    }
    __syncthreads();
    float c = 0.5f * d + x + (w > 0 ? wtot[w - 1] : 0.0f);
    sc[t] = c;
    g_c[b * TT + t] = c;
    g_rinv[b * TT + t] = 1.0f / (rng[b * TT + t] + 1e-6f);
    __syncthreads();

    // --- per-tile windows: binary search on monotone centers ---
    if (t < ntiles) {
        float lob = (float)(t * OT) - MARGIN;
        float hib = (float)(t * OT + OT - 1) + MARGIN;
        int l = 0, r = TT;
        while (l < r) { int m = (l + r) >> 1; if (sc[m] < lob) l = m + 1; else r = m; }
        int lo0 = l;
        l = 0; r = TT;
        while (l < r) { int m = (l + r) >> 1; if (sc[m] <= hib) l = m + 1; else r = m; }
        int hi0 = l - 1;
        if (hi0 - lo0 + 1 > WMAX) hi0 = lo0 + WMAX - 1;  // safety (step>=1 => never)
        g_win[b * MAXTILES + t] = make_int2(lo0, hi0);
    }
}

// ---------------------------------------------------------------------------
// Main: one block per (batch, OT=32 output frames). 4 reps x 96 float4 lanes.
// Weights stored as duplicated pairs {g,g}; accumulators pack column pairs:
//   A[out][cp] += {f_2cp, f_2cp+1} * {g_out, g_out}
// All weight LDS are warp-broadcasts (rep uniform per warp); feat LDG arrives
// naturally packed -> zero duplication MOVs in the inner loop.
// ---------------------------------------------------------------------------
__global__ __launch_bounds__(TUP, 2) void upsample_kernel(const float* __restrict__ feats,
                                                          float* __restrict__ out,
                                                          int outlen) {
    int b = blockIdx.y;
    int tile = blockIdx.x;
    int o0 = tile * OT;
    int tid = threadIdx.x;
    int lane = tid & 31, w = tid >> 5;

    __shared__ __align__(16) float gT2[WMAX * 2 * OT];  // duplicated pairs, 24 KB
    __shared__ float4 scs[D4];                          // combined column sums
    __shared__ float ps[12][OT];
    __shared__ float sInv[OT];
    __shared__ float scc[WMAX], sri[WMAX];
    __shared__ int sLo, sHi;

    int2 win = g_win[b * MAXTILES + tile];
    int lo0 = win.x;
    int width = win.y - win.x + 1;  // may be <= 0 (pure-floor region)
    if (width < 0) width = 0;

    if (tid == 0) { sLo = WMAX; sHi = -1; }
    if (tid < width) {
        scc[tid] = g_c[b * TT + lo0 + tid];
        sri[tid] = g_rinv[b * TT + lo0 + tid];
    }
    // Combine colsum partials once (L2-resident table)
    if (tid < D4) {
        float4 cs = make_float4(0.f, 0.f, 0.f, 0.f);
#pragma unroll
        for (int kc = 0; kc < NCHUNK; kc++) {
            float4 p = g_colpart[kc][b * D4 + tid];
            cs.x += p.x; cs.y += p.y; cs.z += p.z; cs.w += p.w;
        }
        cs.x *= 1e-6f; cs.y *= 1e-6f; cs.z *= 1e-6f; cs.w *= 1e-6f;
        scs[tid] = cs;
    }
    __syncthreads();

    // Phase 1: weights over (j, i) grid, stored duplicated
    int jmin = WMAX, jmax = -1;
    for (int idx = tid; idx < width * OT; idx += TUP) {
        int j = idx >> 5, i = idx & 31;
        float c = scc[j], ri = sri[j];
        float z = ((float)(o0 + i) - c) * ri;
        float gg = __expf(-0.5f * z * z) * (ri * 0.3989422804014327f);
        *(float2*)&gT2[j * (2 * OT) + 2 * i] = make_float2(gg, gg);
        if (gg > 1e-11f) { jmin = min(jmin, j); jmax = max(jmax, j); }
    }
    if (jmax >= 0) { atomicMin(&sLo, jmin); atomicMax(&sHi, jmax); }
    __syncthreads();

    // Row sums: warp w covers j-stripe [8w, 8w+8); lane i < OT accumulates row i.
    {
        float s = 0.0f;
        int j0 = w * 8, j1 = min(width, j0 + 8);
        for (int j = j0; j < j1; j++) s += gT2[j * (2 * OT) + 2 * lane];
        ps[w][lane] = s;
    }
    __syncthreads();
    if (tid < OT) {
        float s = (float)TT * 1e-6f;  // uniform floor mass
#pragma unroll
        for (int ww = 0; ww < 12; ww++) s += ps[ww][tid];
        sInv[tid] = 1.0f / s;
    }
    __syncthreads();

    // Phase 2 setup
    int v = tid % D4;
    int rep = tid / D4;
    int ibase = rep * NOUT;

    unsigned long long A[NOUT][2];
    {
        float4 cs = scs[v];
        float2 lo = make_float2(cs.x, cs.y);
        float2 hi = make_float2(cs.z, cs.w);
        unsigned long long l0 = *(unsigned long long*)&lo;
        unsigned long long h0 = *(unsigned long long*)&hi;
#pragma unroll
        for (int k = 0; k < NOUT; k++) { A[k][0] = l0; A[k][1] = h0; }
    }

    const ulonglong2* f2 = (const ulonglong2*)feats + ((size_t)b * TT + lo0) * D4 + v;
    int jlo = sLo, jhi = sHi;
    if (jlo <= jhi) {
        ulonglong2 f = f2[(size_t)jlo * D4];
        for (int j = jlo; j <= jhi; j++) {
            int jn = (j < jhi) ? (j + 1) : jhi;     // clamped, branch-free prefetch
            ulonglong2 fn = f2[(size_t)jn * D4];
            const ulonglong2* gp = (const ulonglong2*)&gT2[j * (2 * OT) + 2 * ibase];
#pragma unroll
            for (int k = 0; k < NOUT; k += 2) {
                ulonglong2 gd = gp[k >> 1];          // {g_k,g_k},{g_k+1,g_k+1}
                FMA2(A[k][0], f.x, gd.x);
                FMA2(A[k][1], f.y, gd.x);
                FMA2(A[k + 1][0], f.x, gd.y);
                FMA2(A[k + 1][1], f.y, gd.y);
            }
            f = fn;
        }
    }

    // Epilogue: normalize + store (A[k][0]={c0,c1}, A[k][1]={c2,c3})
    float4* out4 = (float4*)out;
#pragma unroll
    for (int k = 0; k < NOUT; k++) {
        int o = o0 + ibase + k;
        if (o < outlen) {
            float s = sInv[ibase + k];
            float4 r;
            r.x = __uint_as_float((unsigned)A[k][0]) * s;
            r.y = __uint_as_float((unsigned)(A[k][0] >> 32)) * s;
            r.z = __uint_as_float((unsigned)A[k][1]) * s;
            r.w = __uint_as_float((unsigned)(A[k][1] >> 32)) * s;
            out4[((size_t)b * outlen + o) * D4 + v] = r;
        }
    }
}

extern "C" void kernel_launch(void* const* d_in, const int* in_sizes, int n_in,
                              void* d_out, int out_size) {
    const float* feats = (const float*)d_in[0];
    const float* rng = (const float*)d_in[1];
    const int* dur = (const int*)d_in[2];
    float* out = (float*)d_out;

    int outlen = out_size / (BB * DD);
    int ntiles = (outlen + OT - 1) / OT;

    prep_kernel<<<dim3(BB, NCHUNK), TT>>>(feats, rng, dur, ntiles);
    upsample_kernel<<<dim3(ntiles, BB), TUP>>>(feats, out, outlen);
}

// round 7
// speedup vs baseline: 1.1820x; 1.1820x over previous
#include <cuda_runtime.h>

#define BB 32
#define TT 512
#define DD 384
#define D4 96
#define OT 32              // output frames per block (two passes of 16)
#define TUP 192            // 2 reps x 96 lanes
#define NOUT 8             // outputs per thread per pass
#define NP 4               // output pairs per thread per pass
#define WMAX 96
#define MAXTILES 128
#define NCHUNK 8
#define MARGIN 30.0f

// Scratch (__device__ globals: no allocations allowed)
__device__ float g_c[BB * TT];                 // gaussian centers (monotone per batch)
__device__ float g_rinv[BB * TT];              // 1/(rng+1e-6)
__device__ float4 g_colpart[NCHUNK][BB * D4];  // partial feats column sums
__device__ int2 g_win[BB * MAXTILES];          // per-tile token windows

#define FMA2(acc, a, b) \
    asm("fma.rn.f32x2 %0, %1, %2, %0;" : "+l"(acc) : "l"(a), "l"(b))
#define DUP(dst, src) \
    asm("mov.b64 %0, {%1, %1};" : "=l"(dst) : "r"(src))

// ---------------------------------------------------------------------------
// Prep, grid (BB, NCHUNK): every block sums its 64-row feats chunk (partials);
// the ky==0 block additionally does the duration scan -> centers/rinv and the
// per-tile window binary searches.
// ---------------------------------------------------------------------------
__global__ __launch_bounds__(TT) void prep_kernel(const float* __restrict__ feats,
                                                  const float* __restrict__ rng,
                                                  const int* __restrict__ dur,
                                                  int ntiles) {
    int b = blockIdx.x, ky = blockIdx.y, t = threadIdx.x;
    int lane = t & 31, w = t >> 5;
    __shared__ float4 part[4][D4];
    __shared__ float sc[TT];
    __shared__ float wtot[16];

    // --- partial column sums: chunk ky = rows [ky*64, ky*64+64), 4 sub-slices ---
    if (t < 384) {
        int v = t % D4, sub = t / D4;
        const float4* f4 = (const float4*)feats + ((size_t)b * TT + ky * 64 + sub * 16) * D4 + v;
        float4 acc = make_float4(0.f, 0.f, 0.f, 0.f);
#pragma unroll
        for (int r = 0; r < 16; r++) {
            float4 f = f4[(size_t)r * D4];
            acc.x += f.x; acc.y += f.y; acc.z += f.z; acc.w += f.w;
        }
        part[sub][v] = acc;
    }
    __syncthreads();
    if (t < D4) {
        float4 acc = part[0][t];
#pragma unroll
        for (int s = 1; s < 4; s++) {
            float4 p = part[s][t];
            acc.x += p.x; acc.y += p.y; acc.z += p.z; acc.w += p.w;
        }
        g_colpart[ky][b * D4 + t] = acc;
    }

    if (ky != 0) return;

    // --- inclusive scan of durations -> centers ---
    float d = (float)dur[b * TT + t];
    float x = d;
#pragma unroll
    for (int off = 1; off < 32; off <<= 1) {
        float y = __shfl_up_sync(0xffffffffu, x, off);
        if (lane >= off) x += y;
    }
    if (lane == 31) wtot[w] = x;
    __syncthreads();
    if (w == 0 && t < 16) {
        float v = wtot[t];
#pragma unroll
        for (int off = 1; off < 16; off <<= 1) {
            float y = __shfl_up_sync(0x0000ffffu, v, off);
            if (t >= off) v += y;
        }
        wtot[t] = v;
    }
    __syncthreads();
    float c = 0.5f * d + x + (w > 0 ? wtot[w - 1] : 0.0f);
    sc[t] = c;
    g_c[b * TT + t] = c;
    g_rinv[b * TT + t] = 1.0f / (rng[b * TT + t] + 1e-6f);
    __syncthreads();

    // --- per-tile (32-output) windows: binary search on monotone centers ---
    if (t < ntiles) {
        float lob = (float)(t * OT) - MARGIN;
        float hib = (float)(t * OT + OT - 1) + MARGIN;
        int l = 0, r = TT;
        while (l < r) { int m = (l + r) >> 1; if (sc[m] < lob) l = m + 1; else r = m; }
        int lo0 = l;
        l = 0; r = TT;
        while (l < r) { int m = (l + r) >> 1; if (sc[m] <= hib) l = m + 1; else r = m; }
        int hi0 = l - 1;
        if (hi0 - lo0 + 1 > WMAX) hi0 = lo0 + WMAX - 1;  // safety (step>=1 => never)
        g_win[b * MAXTILES + t] = make_int2(lo0, hi0);
    }
}

// ---------------------------------------------------------------------------
// Main: one block per (batch, 32 output frames), two sequential 16-output
// passes sharing one weight tile gT[width][32]. Per-thread output column is
// fixed (i = lane since 192 = 6*32), so column sums accumulate for free in
// phase 1. Phase-2 inner loop is identical to the R5 structure (A[col][pair]
// f32x2 packed over output pairs, f duplicated via mov.b64, next-j prefetch).
// ---------------------------------------------------------------------------
__global__ __launch_bounds__(TUP, 5) void upsample_kernel(const float* __restrict__ feats,
                                                          float* __restrict__ out,
                                                          int outlen) {
    int b = blockIdx.y;
    int tile = blockIdx.x;
    int o0 = tile * OT;
    int tid = threadIdx.x;
    int lane = tid & 31, w = tid >> 5;

    __shared__ __align__(16) float gT[WMAX * OT];  // 12 KB, natural [j][i]
    __shared__ float ps[6][OT];
    __shared__ float sInv[OT];
    __shared__ float scc[WMAX], sri[WMAX];
    __shared__ ulonglong2 scs[D4];                 // colsum*1e-6, packed pairs
    __shared__ int sLo[2], sHi[2];

    int2 win = g_win[b * MAXTILES + tile];
    int lo0 = win.x;
    int width = win.y - win.x + 1;  // may be <= 0 (pure-floor region)
    if (width < 0) width = 0;

    if (tid < 2) { sLo[tid] = WMAX; sHi[tid] = -1; }
    if (tid < width) {
        scc[tid] = g_c[b * TT + lo0 + tid];
        sri[tid] = g_rinv[b * TT + lo0 + tid];
    }
    // Combine colsum partials once (L2-resident table), pre-scale by 1e-6
    if (tid < D4) {
        float4 cs = make_float4(0.f, 0.f, 0.f, 0.f);
#pragma unroll
        for (int kc = 0; kc < NCHUNK; kc++) {
            float4 p = g_colpart[kc][b * D4 + tid];
            cs.x += p.x; cs.y += p.y; cs.z += p.z; cs.w += p.w;
        }
        float2 plo = make_float2(cs.x * 1e-6f, cs.y * 1e-6f);
        float2 phi = make_float2(cs.z * 1e-6f, cs.w * 1e-6f);
        ulonglong2 pk;
        pk.x = *(unsigned long long*)&plo;
        pk.y = *(unsigned long long*)&phi;
        scs[tid] = pk;
    }
    __syncthreads();

    // Phase 1: weights over (j, i=lane) grid; per-thread column-sum for free
    float psum = 0.0f;
    int jmin = WMAX, jmax = -1;
    int half = lane >> 4;  // this thread's 16-output half
    float ofr = (float)(o0 + lane);
    for (int idx = tid; idx < width * OT; idx += TUP) {
        int j = idx >> 5;  // idx & 31 == lane (192 = 6*32)
        float c = scc[j], ri = sri[j];
        float z = (ofr - c) * ri;
        float gg = __expf(-0.5f * z * z) * (ri * 0.3989422804014327f);
        gT[idx] = gg;
        psum += gg;
        if (gg > 1e-11f) { jmin = min(jmin, j); jmax = max(jmax, j); }
    }
    ps[w][lane] = psum;
    if (jmax >= 0) { atomicMin(&sLo[half], jmin); atomicMax(&sHi[half], jmax); }
    __syncthreads();

    if (tid < OT) {
        float s = (float)TT * 1e-6f;  // uniform floor mass
#pragma unroll
        for (int ww = 0; ww < 6; ww++) s += ps[ww][tid];
        sInv[tid] = 1.0f / s;
    }
    __syncthreads();

    // Phase 2: two passes of 16 outputs, R5-structured inner loop
    int v = tid % D4;
    int rep = tid / D4;
    const uint4* f4 = (const uint4*)feats + ((size_t)b * TT + lo0) * D4 + v;
    float4* out4 = (float4*)out;

#pragma unroll
    for (int pass = 0; pass < 2; pass++) {
        int ibase = pass * 16 + rep * NOUT;

        unsigned long long A[4][NP];
        {
            ulonglong2 csv = scs[v];
#pragma unroll
            for (int p = 0; p < NP; p++) {
                A[0][p] = csv.x; A[1][p] = csv.x;  // placeholder, fixed below
            }
            // col-major init: A[col][*] where col pairs {0,1}->csv.x halves?
            // csv.x = {cs0,cs1}, csv.y = {cs2,cs3}; accumulator A[col][pair] is
            // scalar col duplicated over the output pair -> need per-col dup:
            unsigned long long d0, d1, d2, d3;
            DUP(d0, (unsigned)(csv.x & 0xffffffffu));
            DUP(d1, (unsigned)(csv.x >> 32));
            DUP(d2, (unsigned)(csv.y & 0xffffffffu));
            DUP(d3, (unsigned)(csv.y >> 32));
#pragma unroll
            for (int p = 0; p < NP; p++) { A[0][p] = d0; A[1][p] = d1; A[2][p] = d2; A[3][p] = d3; }
        }

        int jlo = sLo[pass], jhi = sHi[pass];
        if (jlo <= jhi) {
            uint4 f = f4[(size_t)jlo * D4];
            for (int j = jlo; j <= jhi; j++) {
                int jn = (j < jhi) ? (j + 1) : jhi;  // clamped, branch-free prefetch
                uint4 fn = f4[(size_t)jn * D4];
                unsigned long long fd0, fd1, fd2, fd3;
                DUP(fd0, f.x); DUP(fd1, f.y); DUP(fd2, f.z); DUP(fd3, f.w);
                const ulonglong2* gp = (const ulonglong2*)&gT[j * OT + ibase];
                ulonglong2 gA = gp[0];  // {g0,g1},{g2,g3}
                ulonglong2 gB = gp[1];  // {g4,g5},{g6,g7}
                FMA2(A[0][0], fd0, gA.x); FMA2(A[1][0], fd1, gA.x);
                FMA2(A[2][0], fd2, gA.x); FMA2(A[3][0], fd3, gA.x);
                FMA2(A[0][1], fd0, gA.y); FMA2(A[1][1], fd1, gA.y);
                FMA2(A[2][1], fd2, gA.y); FMA2(A[3][1], fd3, gA.y);
                FMA2(A[0][2], fd0, gB.x); FMA2(A[1][2], fd1, gB.x);
                FMA2(A[2][2], fd2, gB.x); FMA2(A[3][2], fd3, gB.x);
                FMA2(A[0][3], fd0, gB.y); FMA2(A[1][3], fd1, gB.y);
                FMA2(A[2][3], fd2, gB.y); FMA2(A[3][3], fd3, gB.y);
                f = fn;
            }
        }

        // Epilogue: normalize + store (low halves = even output, high = odd)
#pragma unroll
        for (int p = 0; p < NP; p++) {
            int o = o0 + ibase + 2 * p;
            if (o < outlen) {
                float s = sInv[ibase + 2 * p];
                float4 r;
                r.x = __uint_as_float((unsigned)A[0][p]) * s;
                r.y = __uint_as_float((unsigned)A[1][p]) * s;
                r.z = __uint_as_float((unsigned)A[2][p]) * s;
                r.w = __uint_as_float((unsigned)A[3][p]) * s;
                out4[((size_t)b * outlen + o) * D4 + v] = r;
            }
            if (o + 1 < outlen) {
                float s = sInv[ibase + 2 * p + 1];
                float4 r;
                r.x = __uint_as_float((unsigned)(A[0][p] >> 32)) * s;
                r.y = __uint_as_float((unsigned)(A[1][p] >> 32)) * s;
                r.z = __uint_as_float((unsigned)(A[2][p] >> 32)) * s;
                r.w = __uint_as_float((unsigned)(A[3][p] >> 32)) * s;
                out4[((size_t)b * outlen + o + 1) * D4 + v] = r;
            }
        }
    }
}

extern "C" void kernel_launch(void* const* d_in, const int* in_sizes, int n_in,
                              void* d_out, int out_size) {
    const float* feats = (const float*)d_in[0];
    const float* rng = (const float*)d_in[1];
    const int* dur = (const int*)d_in[2];
    float* out = (float*)d_out;

    int outlen = out_size / (BB * DD);
    int ntiles = (outlen + OT - 1) / OT;

    prep_kernel<<<dim3(BB, NCHUNK), TT>>>(feats, rng, dur, ntiles);
    upsample_kernel<<<dim3(ntiles, BB), TUP>>>(feats, out, outlen);
}